// round 2
// baseline (speedup 1.0000x reference)
#include <cuda_runtime.h>
#include <cuda_bf16.h>
#include <cstdint>

// ---------------------------------------------------------------------------
// GCN layer: out = segment_sum((X @ W)[src] * val, dst) + bias
// N_NODES=100000, E=3200000, IN=OUT=128
// Strategy: SGEMM -> build dst-CSR (hist/scan/scatter) -> register aggregation
// (removes all atomic RMW traffic on the 51MB output; SpMM goes from 3.3GB to
//  ~1.7GB of L2 traffic)
// ---------------------------------------------------------------------------

#define IN_DIM  128
#define OUT_DIM 128
#define MAX_NODES 100000
#define MAX_EDGES 3200000

// Scratch (device globals: allocation-free)
__device__ float              g_H[(size_t)MAX_NODES * OUT_DIM];  // 51.2 MB
__device__ int                g_cnt[MAX_NODES];
__device__ int                g_off[MAX_NODES + 1];
__device__ int                g_cur[MAX_NODES];
__device__ unsigned long long g_pairs[MAX_EDGES];                // 25.6 MB (val<<32 | src)

// ---------------------------------------------------------------------------
// Kernel 1: H = X @ W   (tiled SGEMM, BM=128, BN=128, BK=32, 8x8 reg tile)
// ---------------------------------------------------------------------------
#define BM 128
#define BN 128
#define BK 32

__global__ void __launch_bounds__(256, 2)
gemm_kernel(const float* __restrict__ X, const float* __restrict__ W,
            float* __restrict__ H, int N)
{
    __shared__ float sA[BK][BM + 4];
    __shared__ float sB[BK][BN];

    const int tid = threadIdx.x;
    const int tx  = tid & 15;
    const int ty  = tid >> 4;
    const int rowBase = blockIdx.x * BM;

    float acc[8][8];
#pragma unroll
    for (int i = 0; i < 8; i++)
#pragma unroll
        for (int j = 0; j < 8; j++) acc[i][j] = 0.f;

    for (int k0 = 0; k0 < IN_DIM; k0 += BK) {
#pragma unroll
        for (int i = 0; i < 4; i++) {
            int idx = tid + i * 256;
            int m   = idx >> 3;
            int kk  = (idx & 7) << 2;
            int row = rowBase + m;
            float4 v = make_float4(0.f, 0.f, 0.f, 0.f);
            if (row < N)
                v = *(const float4*)&X[(size_t)row * IN_DIM + k0 + kk];
            sA[kk + 0][m] = v.x;
            sA[kk + 1][m] = v.y;
            sA[kk + 2][m] = v.z;
            sA[kk + 3][m] = v.w;
        }
#pragma unroll
        for (int i = 0; i < 4; i++) {
            int idx = tid + i * 256;
            int kk  = idx >> 5;
            int n   = (idx & 31) << 2;
            *(float4*)&sB[kk][n] = *(const float4*)&W[(size_t)(k0 + kk) * OUT_DIM + n];
        }
        __syncthreads();

#pragma unroll
        for (int kk = 0; kk < BK; kk++) {
            float a[8], b[8];
            float4 a0 = *(const float4*)&sA[kk][ty * 8];
            float4 a1 = *(const float4*)&sA[kk][ty * 8 + 4];
            float4 b0 = *(const float4*)&sB[kk][tx * 8];
            float4 b1 = *(const float4*)&sB[kk][tx * 8 + 4];
            a[0]=a0.x; a[1]=a0.y; a[2]=a0.z; a[3]=a0.w;
            a[4]=a1.x; a[5]=a1.y; a[6]=a1.z; a[7]=a1.w;
            b[0]=b0.x; b[1]=b0.y; b[2]=b0.z; b[3]=b0.w;
            b[4]=b1.x; b[5]=b1.y; b[6]=b1.z; b[7]=b1.w;
#pragma unroll
            for (int i = 0; i < 8; i++)
#pragma unroll
                for (int j = 0; j < 8; j++)
                    acc[i][j] += a[i] * b[j];
        }
        __syncthreads();
    }

#pragma unroll
    for (int i = 0; i < 8; i++) {
        int row = rowBase + ty * 8 + i;
        if (row < N) {
            float* p = &H[(size_t)row * OUT_DIM + tx * 8];
            *(float4*)p       = make_float4(acc[i][0], acc[i][1], acc[i][2], acc[i][3]);
            *(float4*)(p + 4) = make_float4(acc[i][4], acc[i][5], acc[i][6], acc[i][7]);
        }
    }
}

// ---------------------------------------------------------------------------
// CSR build
// ---------------------------------------------------------------------------
__global__ void __launch_bounds__(256)
zero_cnt_kernel(int N)
{
    int i = blockIdx.x * blockDim.x + threadIdx.x;
    if (i < N) g_cnt[i] = 0;
}

__global__ void __launch_bounds__(256)
hist_kernel(const int* __restrict__ dst, int E)
{
    int i = blockIdx.x * blockDim.x + threadIdx.x;
    int stride = gridDim.x * blockDim.x;
    for (; i < E; i += stride)
        atomicAdd(&g_cnt[dst[i]], 1);
}

#define SCAN_T 1024
__global__ void __launch_bounds__(SCAN_T)
scan_kernel(int N)
{
    __shared__ int ssum[SCAN_T];
    int t = threadIdx.x;
    int chunk = (N + SCAN_T - 1) / SCAN_T;
    int beg = t * chunk;
    int end = min(beg + chunk, N);

    int s = 0;
    for (int i = beg; i < end; i++) s += g_cnt[i];
    ssum[t] = s;
    __syncthreads();

    // Hillis-Steele inclusive scan
#pragma unroll
    for (int d = 1; d < SCAN_T; d <<= 1) {
        int v = (t >= d) ? ssum[t - d] : 0;
        __syncthreads();
        ssum[t] += v;
        __syncthreads();
    }

    int run = ssum[t] - s;   // exclusive prefix
    for (int i = beg; i < end; i++) {
        g_off[i] = run;
        g_cur[i] = run;
        run += g_cnt[i];
    }
    if (t == SCAN_T - 1) g_off[N] = run;
}

__global__ void __launch_bounds__(256)
scatter_kernel(const int* __restrict__ src, const int* __restrict__ dst,
               const float* __restrict__ val, int E)
{
    int i = blockIdx.x * blockDim.x + threadIdx.x;
    int stride = gridDim.x * blockDim.x;
    for (; i < E; i += stride) {
        int d = dst[i];
        int pos = atomicAdd(&g_cur[d], 1);
        g_pairs[pos] = ((unsigned long long)__float_as_uint(val[i]) << 32)
                     | (unsigned int)src[i];
    }
}

// ---------------------------------------------------------------------------
// Aggregation: one warp per dst node, register accumulators, bias folded in.
// Software-pipelined pair prefetch + 2-edge unroll (MLP >= 2 on H gathers).
// ---------------------------------------------------------------------------
__global__ void __launch_bounds__(256)
agg_kernel(const float* __restrict__ H, const float* __restrict__ bias,
           float* __restrict__ out, int N)
{
    const int lane = threadIdx.x & 31;
    const int w    = (blockIdx.x * blockDim.x + threadIdx.x) >> 5;
    if (w >= N) return;

    const int beg = g_off[w];
    const int end = g_off[w + 1];

    float4 acc0 = *(const float4*)&bias[lane * 4];
    float4 acc1 = make_float4(0.f, 0.f, 0.f, 0.f);

    int e = beg;
    unsigned long long p0 = 0, p1 = 0;
    if (e     < end) p0 = __ldg(&g_pairs[e]);
    if (e + 1 < end) p1 = __ldg(&g_pairs[e + 1]);

    while (e + 2 <= end) {
        const int   s0 = (int)(unsigned int)p0;
        const float v0 = __uint_as_float((unsigned int)(p0 >> 32));
        const int   s1 = (int)(unsigned int)p1;
        const float v1 = __uint_as_float((unsigned int)(p1 >> 32));

        const float4 h0 = __ldg((const float4*)(H + (size_t)s0 * OUT_DIM) + lane);
        const float4 h1 = __ldg((const float4*)(H + (size_t)s1 * OUT_DIM) + lane);

        // prefetch next pair while h0/h1 are in flight
        if (e + 2 < end) p0 = __ldg(&g_pairs[e + 2]);
        if (e + 3 < end) p1 = __ldg(&g_pairs[e + 3]);

        acc0.x += v0 * h0.x; acc0.y += v0 * h0.y;
        acc0.z += v0 * h0.z; acc0.w += v0 * h0.w;
        acc1.x += v1 * h1.x; acc1.y += v1 * h1.y;
        acc1.z += v1 * h1.z; acc1.w += v1 * h1.w;
        e += 2;
    }
    if (e < end) {
        const int   s0 = (int)(unsigned int)p0;
        const float v0 = __uint_as_float((unsigned int)(p0 >> 32));
        const float4 h0 = __ldg((const float4*)(H + (size_t)s0 * OUT_DIM) + lane);
        acc0.x += v0 * h0.x; acc0.y += v0 * h0.y;
        acc0.z += v0 * h0.z; acc0.w += v0 * h0.w;
    }

    acc0.x += acc1.x; acc0.y += acc1.y; acc0.z += acc1.z; acc0.w += acc1.w;
    *(float4*)&out[(size_t)w * OUT_DIM + lane * 4] = acc0;
}

// ---------------------------------------------------------------------------
// Launch
// ---------------------------------------------------------------------------
extern "C" void kernel_launch(void* const* d_in, const int* in_sizes, int n_in,
                              void* d_out, int out_size)
{
    const float* features  = (const float*)d_in[0];
    const int*   edge_src  = (const int*)  d_in[1];
    const int*   edge_dst  = (const int*)  d_in[2];
    const float* edge_vals = (const float*)d_in[3];
    const float* weight    = (const float*)d_in[4];
    const float* bias      = (const float*)d_in[5];
    float*       out       = (float*)d_out;

    const int N = in_sizes[0] / IN_DIM;     // 100000
    const int E = in_sizes[1];              // 3200000

    float* H;
    cudaGetSymbolAddress((void**)&H, g_H);

    // 1) H = X @ W
    gemm_kernel<<<(N + BM - 1) / BM, 256>>>(features, weight, H, N);

    // 2) CSR build: zero -> histogram -> scan -> scatter
    zero_cnt_kernel<<<(N + 255) / 256, 256>>>(N);
    hist_kernel<<<1184, 256>>>(edge_dst, E);
    scan_kernel<<<1, SCAN_T>>>(N);
    scatter_kernel<<<1184, 256>>>(edge_src, edge_dst, edge_vals, E);

    // 3) Aggregate: one warp per node (bias folded in)
    int agg_blocks = (N * 32 + 255) / 256;
    agg_kernel<<<agg_blocks, 256>>>(H, bias, out, N);
}

// round 3
// speedup vs baseline: 1.5539x; 1.5539x over previous
#include <cuda_runtime.h>
#include <cuda_bf16.h>
#include <cstdint>

// ---------------------------------------------------------------------------
// GCN layer: out = segment_sum((X @ W)[src] * val, dst) + bias
// N_NODES=100000, E=3200000, IN=OUT=128
// SGEMM -> dst-CSR build (hist / 3-phase parallel scan / scatter)
//       -> register aggregation (one warp per node, bias folded)
// ---------------------------------------------------------------------------

#define IN_DIM  128
#define OUT_DIM 128
#define MAX_NODES 100000
#define MAX_EDGES 3200000
#define SB 256                      // scan block size
#define MAX_BLKS 512                // >= ceil(MAX_NODES/SB) = 391

// Scratch (device globals: allocation-free)
__device__ float              g_H[(size_t)MAX_NODES * OUT_DIM];  // 51.2 MB
__device__ int                g_cnt[MAX_NODES];
__device__ int                g_off[MAX_NODES + 1];
__device__ int                g_cur[MAX_NODES];
__device__ int                g_blk[MAX_BLKS];
__device__ int                g_blkoff[MAX_BLKS];
__device__ unsigned long long g_pairs[MAX_EDGES];                // (val<<32 | src)

// ---------------------------------------------------------------------------
// Kernel 1: H = X @ W   (tiled SGEMM, BM=128, BN=128, BK=32, 8x8 reg tile)
// ---------------------------------------------------------------------------
#define BM 128
#define BN 128
#define BK 32

__global__ void __launch_bounds__(256, 2)
gemm_kernel(const float* __restrict__ X, const float* __restrict__ W,
            float* __restrict__ H, int N)
{
    __shared__ float sA[BK][BM + 4];
    __shared__ float sB[BK][BN];

    const int tid = threadIdx.x;
    const int tx  = tid & 15;
    const int ty  = tid >> 4;
    const int rowBase = blockIdx.x * BM;

    float acc[8][8];
#pragma unroll
    for (int i = 0; i < 8; i++)
#pragma unroll
        for (int j = 0; j < 8; j++) acc[i][j] = 0.f;

    for (int k0 = 0; k0 < IN_DIM; k0 += BK) {
#pragma unroll
        for (int i = 0; i < 4; i++) {
            int idx = tid + i * 256;
            int m   = idx >> 3;
            int kk  = (idx & 7) << 2;
            int row = rowBase + m;
            float4 v = make_float4(0.f, 0.f, 0.f, 0.f);
            if (row < N)
                v = *(const float4*)&X[(size_t)row * IN_DIM + k0 + kk];
            sA[kk + 0][m] = v.x;
            sA[kk + 1][m] = v.y;
            sA[kk + 2][m] = v.z;
            sA[kk + 3][m] = v.w;
        }
#pragma unroll
        for (int i = 0; i < 4; i++) {
            int idx = tid + i * 256;
            int kk  = idx >> 5;
            int n   = (idx & 31) << 2;
            *(float4*)&sB[kk][n] = *(const float4*)&W[(size_t)(k0 + kk) * OUT_DIM + n];
        }
        __syncthreads();

#pragma unroll
        for (int kk = 0; kk < BK; kk++) {
            float a[8], b[8];
            float4 a0 = *(const float4*)&sA[kk][ty * 8];
            float4 a1 = *(const float4*)&sA[kk][ty * 8 + 4];
            float4 b0 = *(const float4*)&sB[kk][tx * 8];
            float4 b1 = *(const float4*)&sB[kk][tx * 8 + 4];
            a[0]=a0.x; a[1]=a0.y; a[2]=a0.z; a[3]=a0.w;
            a[4]=a1.x; a[5]=a1.y; a[6]=a1.z; a[7]=a1.w;
            b[0]=b0.x; b[1]=b0.y; b[2]=b0.z; b[3]=b0.w;
            b[4]=b1.x; b[5]=b1.y; b[6]=b1.z; b[7]=b1.w;
#pragma unroll
            for (int i = 0; i < 8; i++)
#pragma unroll
                for (int j = 0; j < 8; j++)
                    acc[i][j] += a[i] * b[j];
        }
        __syncthreads();
    }

#pragma unroll
    for (int i = 0; i < 8; i++) {
        int row = rowBase + ty * 8 + i;
        if (row < N) {
            float* p = &H[(size_t)row * OUT_DIM + tx * 8];
            *(float4*)p       = make_float4(acc[i][0], acc[i][1], acc[i][2], acc[i][3]);
            *(float4*)(p + 4) = make_float4(acc[i][4], acc[i][5], acc[i][6], acc[i][7]);
        }
    }
}

// ---------------------------------------------------------------------------
// CSR build
// ---------------------------------------------------------------------------
__global__ void __launch_bounds__(256)
zero_cnt_kernel(int N)
{
    int i = blockIdx.x * blockDim.x + threadIdx.x;
    if (i < N) g_cnt[i] = 0;
}

__global__ void __launch_bounds__(256)
hist_kernel(const int* __restrict__ dst, int E)
{
    int i = blockIdx.x * blockDim.x + threadIdx.x;
    int stride = gridDim.x * blockDim.x;
    for (; i < E; i += stride)
        atomicAdd(&g_cnt[dst[i]], 1);
}

// --- 3-phase parallel scan of g_cnt -> g_off / g_cur ---

// Phase A: per-block sums
__global__ void __launch_bounds__(SB)
blksum_kernel(int N)
{
    __shared__ int s[SB];
    int i = blockIdx.x * SB + threadIdx.x;
    s[threadIdx.x] = (i < N) ? g_cnt[i] : 0;
    __syncthreads();
#pragma unroll
    for (int d = SB / 2; d > 0; d >>= 1) {
        if (threadIdx.x < d) s[threadIdx.x] += s[threadIdx.x + d];
        __syncthreads();
    }
    if (threadIdx.x == 0) g_blk[blockIdx.x] = s[0];
}

// Phase B: single-block scan of block sums (nblk <= MAX_BLKS = 512)
__global__ void __launch_bounds__(MAX_BLKS)
blkscan_kernel(int nblk, int N, int E)
{
    __shared__ int s[MAX_BLKS];
    int t = threadIdx.x;
    int v = (t < nblk) ? g_blk[t] : 0;
    s[t] = v;
    __syncthreads();
#pragma unroll
    for (int d = 1; d < MAX_BLKS; d <<= 1) {
        int u = (t >= d) ? s[t - d] : 0;
        __syncthreads();
        s[t] += u;
        __syncthreads();
    }
    if (t < nblk) g_blkoff[t] = s[t] - v;   // exclusive prefix
    if (t == 0) g_off[N] = E;
}

// Phase C: per-block local exclusive scan + block offset
__global__ void __launch_bounds__(SB)
local_scan_kernel(int N)
{
    __shared__ int s[SB];
    int i = blockIdx.x * SB + threadIdx.x;
    int c = (i < N) ? g_cnt[i] : 0;
    s[threadIdx.x] = c;
    __syncthreads();
#pragma unroll
    for (int d = 1; d < SB; d <<= 1) {
        int u = (threadIdx.x >= d) ? s[threadIdx.x - d] : 0;
        __syncthreads();
        s[threadIdx.x] += u;
        __syncthreads();
    }
    if (i < N) {
        int off = g_blkoff[blockIdx.x] + s[threadIdx.x] - c;  // exclusive
        g_off[i] = off;
        g_cur[i] = off;
    }
}

__global__ void __launch_bounds__(256)
scatter_kernel(const int* __restrict__ src, const int* __restrict__ dst,
               const float* __restrict__ val, int E)
{
    int i = blockIdx.x * blockDim.x + threadIdx.x;
    int stride = gridDim.x * blockDim.x;
    for (; i < E; i += stride) {
        int d = dst[i];
        int pos = atomicAdd(&g_cur[d], 1);
        g_pairs[pos] = ((unsigned long long)__float_as_uint(val[i]) << 32)
                     | (unsigned int)src[i];
    }
}

// ---------------------------------------------------------------------------
// Aggregation: one warp per dst node, register accumulators, bias folded in.
// ---------------------------------------------------------------------------
__global__ void __launch_bounds__(256)
agg_kernel(const float* __restrict__ H, const float* __restrict__ bias,
           float* __restrict__ out, int N)
{
    const int lane = threadIdx.x & 31;
    const int w    = (blockIdx.x * blockDim.x + threadIdx.x) >> 5;
    if (w >= N) return;

    const int beg = g_off[w];
    const int end = g_off[w + 1];

    float4 acc0 = *(const float4*)&bias[lane * 4];
    float4 acc1 = make_float4(0.f, 0.f, 0.f, 0.f);

    int e = beg;
    unsigned long long p0 = 0, p1 = 0;
    if (e     < end) p0 = __ldg(&g_pairs[e]);
    if (e + 1 < end) p1 = __ldg(&g_pairs[e + 1]);

    while (e + 2 <= end) {
        const int   s0 = (int)(unsigned int)p0;
        const float v0 = __uint_as_float((unsigned int)(p0 >> 32));
        const int   s1 = (int)(unsigned int)p1;
        const float v1 = __uint_as_float((unsigned int)(p1 >> 32));

        const float4 h0 = __ldg((const float4*)(H + (size_t)s0 * OUT_DIM) + lane);
        const float4 h1 = __ldg((const float4*)(H + (size_t)s1 * OUT_DIM) + lane);

        if (e + 2 < end) p0 = __ldg(&g_pairs[e + 2]);
        if (e + 3 < end) p1 = __ldg(&g_pairs[e + 3]);

        acc0.x += v0 * h0.x; acc0.y += v0 * h0.y;
        acc0.z += v0 * h0.z; acc0.w += v0 * h0.w;
        acc1.x += v1 * h1.x; acc1.y += v1 * h1.y;
        acc1.z += v1 * h1.z; acc1.w += v1 * h1.w;
        e += 2;
    }
    if (e < end) {
        const int   s0 = (int)(unsigned int)p0;
        const float v0 = __uint_as_float((unsigned int)(p0 >> 32));
        const float4 h0 = __ldg((const float4*)(H + (size_t)s0 * OUT_DIM) + lane);
        acc0.x += v0 * h0.x; acc0.y += v0 * h0.y;
        acc0.z += v0 * h0.z; acc0.w += v0 * h0.w;
    }

    acc0.x += acc1.x; acc0.y += acc1.y; acc0.z += acc1.z; acc0.w += acc1.w;
    *(float4*)&out[(size_t)w * OUT_DIM + lane * 4] = acc0;
}

// ---------------------------------------------------------------------------
// Launch
// ---------------------------------------------------------------------------
extern "C" void kernel_launch(void* const* d_in, const int* in_sizes, int n_in,
                              void* d_out, int out_size)
{
    const float* features  = (const float*)d_in[0];
    const int*   edge_src  = (const int*)  d_in[1];
    const int*   edge_dst  = (const int*)  d_in[2];
    const float* edge_vals = (const float*)d_in[3];
    const float* weight    = (const float*)d_in[4];
    const float* bias      = (const float*)d_in[5];
    float*       out       = (float*)d_out;

    const int N = in_sizes[0] / IN_DIM;     // 100000
    const int E = in_sizes[1];              // 3200000

    float* H;
    cudaGetSymbolAddress((void**)&H, g_H);

    // 1) H = X @ W
    gemm_kernel<<<(N + BM - 1) / BM, 256>>>(features, weight, H, N);

    // 2) CSR build
    int nblk = (N + SB - 1) / SB;           // 391
    zero_cnt_kernel<<<(N + 255) / 256, 256>>>(N);
    hist_kernel<<<1184, 256>>>(edge_dst, E);
    blksum_kernel<<<nblk, SB>>>(N);
    blkscan_kernel<<<1, MAX_BLKS>>>(nblk, N, E);
    local_scan_kernel<<<nblk, SB>>>(N);
    scatter_kernel<<<1184, 256>>>(edge_src, edge_dst, edge_vals, E);

    // 3) Aggregate: one warp per node (bias folded in)
    int agg_blocks = (N * 32 + 255) / 256;
    agg_kernel<<<agg_blocks, 256>>>(H, bias, out, N);
}

// round 4
// speedup vs baseline: 1.7667x; 1.1369x over previous
#include <cuda_runtime.h>
#include <cuda_fp16.h>
#include <cuda_bf16.h>
#include <cstdint>

// ---------------------------------------------------------------------------
// GCN layer: out = segment_sum((X @ W)[src] * val, dst) + bias
// N_NODES=100000, E=3200000, IN=OUT=128
// SGEMM (packed f32x2 FMA, fp16 output) -> dst-CSR build -> fp16-gather
// register aggregation (one warp per node, fp32 accumulate, bias folded)
// ---------------------------------------------------------------------------

#define IN_DIM  128
#define OUT_DIM 128
#define MAX_NODES 100000
#define MAX_EDGES 3200000
#define SB 256
#define MAX_BLKS 512

// Scratch (device globals: allocation-free)
__device__ __half             g_H[(size_t)MAX_NODES * OUT_DIM];  // 25.6 MB fp16
__device__ int                g_cnt[MAX_NODES];
__device__ int                g_off[MAX_NODES + 1];
__device__ int                g_cur[MAX_NODES];
__device__ int                g_blk[MAX_BLKS];
__device__ int                g_blkoff[MAX_BLKS];
__device__ unsigned long long g_pairs[MAX_EDGES];                // (val<<32 | src)

// --- packed fp32x2 helpers (sm_103a FFMA2 path, only reachable via PTX) ---
__device__ __forceinline__ unsigned long long f32x2_dup(float x) {
    unsigned long long r;
    asm("mov.b64 %0, {%1, %1};" : "=l"(r) : "f"(x));
    return r;
}
__device__ __forceinline__ void ffma2(unsigned long long& d,
                                      unsigned long long a,
                                      unsigned long long b) {
    asm("fma.rn.f32x2 %0, %1, %2, %0;" : "+l"(d) : "l"(a), "l"(b));
}
__device__ __forceinline__ float2 f32x2_unpack(unsigned long long v) {
    float lo, hi;
    asm("mov.b64 {%0, %1}, %2;" : "=f"(lo), "=f"(hi) : "l"(v));
    return make_float2(lo, hi);
}

// ---------------------------------------------------------------------------
// Kernel 1: H = X @ W  (BM=128, BN=128, BK=32, 8x8 reg tile, FFMA2 math,
//                       fp16 output)
// ---------------------------------------------------------------------------
#define BM 128
#define BN 128
#define BK 32

__global__ void __launch_bounds__(256, 2)
gemm_kernel(const float* __restrict__ X, const float* __restrict__ W,
            __half* __restrict__ H, int N)
{
    __shared__ float sA[BK][BM + 4];
    __shared__ float sB[BK][BN];

    const int tid = threadIdx.x;
    const int tx  = tid & 15;
    const int ty  = tid >> 4;
    const int rowBase = blockIdx.x * BM;

    unsigned long long acc[8][4];   // 8 rows x 4 f32x2 (= 8 cols)
#pragma unroll
    for (int i = 0; i < 8; i++)
#pragma unroll
        for (int j = 0; j < 4; j++) acc[i][j] = 0ull;

    for (int k0 = 0; k0 < IN_DIM; k0 += BK) {
#pragma unroll
        for (int i = 0; i < 4; i++) {
            int idx = tid + i * 256;
            int m   = idx >> 3;
            int kk  = (idx & 7) << 2;
            int row = rowBase + m;
            float4 v = make_float4(0.f, 0.f, 0.f, 0.f);
            if (row < N)
                v = *(const float4*)&X[(size_t)row * IN_DIM + k0 + kk];
            sA[kk + 0][m] = v.x;
            sA[kk + 1][m] = v.y;
            sA[kk + 2][m] = v.z;
            sA[kk + 3][m] = v.w;
        }
#pragma unroll
        for (int i = 0; i < 4; i++) {
            int idx = tid + i * 256;
            int kk  = idx >> 5;
            int n   = (idx & 31) << 2;
            *(float4*)&sB[kk][n] = *(const float4*)&W[(size_t)(k0 + kk) * OUT_DIM + n];
        }
        __syncthreads();

#pragma unroll
        for (int kk = 0; kk < BK; kk++) {
            float4 a0 = *(const float4*)&sA[kk][ty * 8];
            float4 a1 = *(const float4*)&sA[kk][ty * 8 + 4];
            // b as 4 packed f32x2 (pairs are register-adjacent from LDS.128)
            ulonglong2 bb0 = *(const ulonglong2*)&sB[kk][tx * 8];
            ulonglong2 bb1 = *(const ulonglong2*)&sB[kk][tx * 8 + 4];
            unsigned long long b[4] = {bb0.x, bb0.y, bb1.x, bb1.y};

            unsigned long long ad[8];
            ad[0] = f32x2_dup(a0.x); ad[1] = f32x2_dup(a0.y);
            ad[2] = f32x2_dup(a0.z); ad[3] = f32x2_dup(a0.w);
            ad[4] = f32x2_dup(a1.x); ad[5] = f32x2_dup(a1.y);
            ad[6] = f32x2_dup(a1.z); ad[7] = f32x2_dup(a1.w);
#pragma unroll
            for (int i = 0; i < 8; i++)
#pragma unroll
                for (int j = 0; j < 4; j++)
                    ffma2(acc[i][j], ad[i], b[j]);
        }
        __syncthreads();
    }

    // Store 8x8 tile as fp16 (8 halves = 16B per row-chunk)
#pragma unroll
    for (int i = 0; i < 8; i++) {
        int row = rowBase + ty * 8 + i;
        if (row < N) {
            __half2 h[4];
#pragma unroll
            for (int j = 0; j < 4; j++) {
                float2 f = f32x2_unpack(acc[i][j]);
                h[j] = __floats2half2_rn(f.x, f.y);
            }
            *(uint4*)&H[(size_t)row * OUT_DIM + tx * 8] = *(uint4*)h;
        }
    }
}

// ---------------------------------------------------------------------------
// CSR build
// ---------------------------------------------------------------------------
__global__ void __launch_bounds__(256)
zero_cnt_kernel(int N)
{
    int i = blockIdx.x * blockDim.x + threadIdx.x;
    if (i < N) g_cnt[i] = 0;
}

__global__ void __launch_bounds__(256)
hist_kernel(const int* __restrict__ dst, int E)
{
    int i = blockIdx.x * blockDim.x + threadIdx.x;
    int stride = gridDim.x * blockDim.x;
    for (; i < E; i += stride)
        atomicAdd(&g_cnt[dst[i]], 1);
}

__global__ void __launch_bounds__(SB)
blksum_kernel(int N)
{
    __shared__ int s[SB];
    int i = blockIdx.x * SB + threadIdx.x;
    s[threadIdx.x] = (i < N) ? g_cnt[i] : 0;
    __syncthreads();
#pragma unroll
    for (int d = SB / 2; d > 0; d >>= 1) {
        if (threadIdx.x < d) s[threadIdx.x] += s[threadIdx.x + d];
        __syncthreads();
    }
    if (threadIdx.x == 0) g_blk[blockIdx.x] = s[0];
}

__global__ void __launch_bounds__(MAX_BLKS)
blkscan_kernel(int nblk, int N, int E)
{
    __shared__ int s[MAX_BLKS];
    int t = threadIdx.x;
    int v = (t < nblk) ? g_blk[t] : 0;
    s[t] = v;
    __syncthreads();
#pragma unroll
    for (int d = 1; d < MAX_BLKS; d <<= 1) {
        int u = (t >= d) ? s[t - d] : 0;
        __syncthreads();
        s[t] += u;
        __syncthreads();
    }
    if (t < nblk) g_blkoff[t] = s[t] - v;
    if (t == 0) g_off[N] = E;
}

__global__ void __launch_bounds__(SB)
local_scan_kernel(int N)
{
    __shared__ int s[SB];
    int i = blockIdx.x * SB + threadIdx.x;
    int c = (i < N) ? g_cnt[i] : 0;
    s[threadIdx.x] = c;
    __syncthreads();
#pragma unroll
    for (int d = 1; d < SB; d <<= 1) {
        int u = (threadIdx.x >= d) ? s[threadIdx.x - d] : 0;
        __syncthreads();
        s[threadIdx.x] += u;
        __syncthreads();
    }
    if (i < N) {
        int off = g_blkoff[blockIdx.x] + s[threadIdx.x] - c;
        g_off[i] = off;
        g_cur[i] = off;
    }
}

__global__ void __launch_bounds__(256)
scatter_kernel(const int* __restrict__ src, const int* __restrict__ dst,
               const float* __restrict__ val, int E)
{
    int i = blockIdx.x * blockDim.x + threadIdx.x;
    int stride = gridDim.x * blockDim.x;
    for (; i < E; i += stride) {
        int d = dst[i];
        int pos = atomicAdd(&g_cur[d], 1);
        g_pairs[pos] = ((unsigned long long)__float_as_uint(val[i]) << 32)
                     | (unsigned int)src[i];
    }
}

// ---------------------------------------------------------------------------
// Aggregation: one warp per dst node, fp16 H gather (256B/edge), fp32 accum.
// ---------------------------------------------------------------------------
__global__ void __launch_bounds__(256)
agg_kernel(const __half* __restrict__ H, const float* __restrict__ bias,
           float* __restrict__ out, int N)
{
    const int lane = threadIdx.x & 31;
    const int w    = (blockIdx.x * blockDim.x + threadIdx.x) >> 5;
    if (w >= N) return;

    const int beg = g_off[w];
    const int end = g_off[w + 1];

    float4 acc0 = *(const float4*)&bias[lane * 4];
    float4 acc1 = make_float4(0.f, 0.f, 0.f, 0.f);

    int e = beg;
    unsigned long long p0 = 0, p1 = 0;
    if (e     < end) p0 = __ldg(&g_pairs[e]);
    if (e + 1 < end) p1 = __ldg(&g_pairs[e + 1]);

    while (e + 2 <= end) {
        const int   s0 = (int)(unsigned int)p0;
        const float v0 = __uint_as_float((unsigned int)(p0 >> 32));
        const int   s1 = (int)(unsigned int)p1;
        const float v1 = __uint_as_float((unsigned int)(p1 >> 32));

        const uint2 u0 = __ldg((const uint2*)(H + (size_t)s0 * OUT_DIM) + lane);
        const uint2 u1 = __ldg((const uint2*)(H + (size_t)s1 * OUT_DIM) + lane);

        if (e + 2 < end) p0 = __ldg(&g_pairs[e + 2]);
        if (e + 3 < end) p1 = __ldg(&g_pairs[e + 3]);

        float2 f0a = __half22float2(*(const __half2*)&u0.x);
        float2 f0b = __half22float2(*(const __half2*)&u0.y);
        float2 f1a = __half22float2(*(const __half2*)&u1.x);
        float2 f1b = __half22float2(*(const __half2*)&u1.y);

        acc0.x += v0 * f0a.x; acc0.y += v0 * f0a.y;
        acc0.z += v0 * f0b.x; acc0.w += v0 * f0b.y;
        acc1.x += v1 * f1a.x; acc1.y += v1 * f1a.y;
        acc1.z += v1 * f1b.x; acc1.w += v1 * f1b.y;
        e += 2;
    }
    if (e < end) {
        const int   s0 = (int)(unsigned int)p0;
        const float v0 = __uint_as_float((unsigned int)(p0 >> 32));
        const uint2 u0 = __ldg((const uint2*)(H + (size_t)s0 * OUT_DIM) + lane);
        float2 f0a = __half22float2(*(const __half2*)&u0.x);
        float2 f0b = __half22float2(*(const __half2*)&u0.y);
        acc0.x += v0 * f0a.x; acc0.y += v0 * f0a.y;
        acc0.z += v0 * f0b.x; acc0.w += v0 * f0b.y;
    }

    acc0.x += acc1.x; acc0.y += acc1.y; acc0.z += acc1.z; acc0.w += acc1.w;
    *(float4*)&out[(size_t)w * OUT_DIM + lane * 4] = acc0;
}

// ---------------------------------------------------------------------------
// Launch
// ---------------------------------------------------------------------------
extern "C" void kernel_launch(void* const* d_in, const int* in_sizes, int n_in,
                              void* d_out, int out_size)
{
    const float* features  = (const float*)d_in[0];
    const int*   edge_src  = (const int*)  d_in[1];
    const int*   edge_dst  = (const int*)  d_in[2];
    const float* edge_vals = (const float*)d_in[3];
    const float* weight    = (const float*)d_in[4];
    const float* bias      = (const float*)d_in[5];
    float*       out       = (float*)d_out;

    const int N = in_sizes[0] / IN_DIM;     // 100000
    const int E = in_sizes[1];              // 3200000

    __half* H;
    cudaGetSymbolAddress((void**)&H, g_H);

    // 1) H = X @ W  (fp16 out)
    gemm_kernel<<<(N + BM - 1) / BM, 256>>>(features, weight, H, N);

    // 2) CSR build
    int nblk = (N + SB - 1) / SB;           // 391
    zero_cnt_kernel<<<(N + 255) / 256, 256>>>(N);
    hist_kernel<<<1184, 256>>>(edge_dst, E);
    blksum_kernel<<<nblk, SB>>>(N);
    blkscan_kernel<<<1, MAX_BLKS>>>(nblk, N, E);
    local_scan_kernel<<<nblk, SB>>>(N);
    scatter_kernel<<<1184, 256>>>(edge_src, edge_dst, edge_vals, E);

    // 3) Aggregate: one warp per node (bias folded in)
    int agg_blocks = (N * 32 + 255) / 256;
    agg_kernel<<<agg_blocks, 256>>>(H, bias, out, N);
}

// round 5
// speedup vs baseline: 2.3278x; 1.3176x over previous
#include <cuda_runtime.h>
#include <cuda_fp16.h>
#include <cuda_bf16.h>
#include <mma.h>
#include <cstdint>

using namespace nvcuda;

// ---------------------------------------------------------------------------
// GCN layer: out = segment_sum((X @ W)[src] * val, dst) + bias
// N_NODES=100000, E=3200000, IN=OUT=128
// Tensor-core GEMM (fp16 in / fp32 accum / fp16 out) -> dst-CSR build ->
// fp16-gather register aggregation (4-deep pipeline, fp32 accum, bias folded)
// ---------------------------------------------------------------------------

#define IN_DIM  128
#define OUT_DIM 128
#define MAX_NODES 100000
#define MAX_EDGES 3200000
#define SB 256
#define MAX_BLKS 512

// Scratch (device globals: allocation-free)
__device__ __half             g_H[(size_t)MAX_NODES * OUT_DIM];  // 25.6 MB fp16
__device__ int                g_cnt[MAX_NODES];
__device__ int                g_off[MAX_NODES + 1];
__device__ int                g_cur[MAX_NODES];
__device__ int                g_blk[MAX_BLKS];
__device__ int                g_blkoff[MAX_BLKS];
__device__ unsigned long long g_pairs[MAX_EDGES];                // (val<<32 | src)

// ---------------------------------------------------------------------------
// Kernel 1: H = X @ W  via wmma HMMA. Block = 128 rows, full K=128 in smem.
// 8 warps; each warp computes a 32x64 tile as 2x4 wmma 16x16x16 fragments.
// smem: sA 128x136 half (34816B) + sB 128x136 half (34816B) + patch 8KB.
// ---------------------------------------------------------------------------
#define GEMM_SMEM (34816 + 34816 + 8192)

__global__ void __launch_bounds__(256, 2)
gemm_kernel(const float* __restrict__ X, const float* __restrict__ W,
            __half* __restrict__ H, int N)
{
    extern __shared__ char smem_raw[];
    __half (*sA)[136] = (__half(*)[136])(smem_raw);
    __half (*sB)[136] = (__half(*)[136])(smem_raw + 34816);
    float  (*patch)[16][16] = (float(*)[16][16])(smem_raw + 69632);

    const int tid  = threadIdx.x;
    const int lane = tid & 31;
    const int warp = tid >> 5;      // 0..7
    const int wm   = warp >> 1;     // 0..3 : 32-row group
    const int wn   = warp & 1;      // 0..1 : 64-col group
    const int rowBase = blockIdx.x * 128;

    // Stage X block -> sA (fp32 -> fp16)
#pragma unroll
    for (int i = 0; i < 16; i++) {
        int idx = tid + i * 256;            // 0..4095
        int m   = idx >> 5;                 // row in tile
        int c4  = idx & 31;                 // float4 index in row
        int row = rowBase + m;
        float4 v = (row < N) ? *(const float4*)&X[(size_t)row * IN_DIM + c4 * 4]
                             : make_float4(0.f, 0.f, 0.f, 0.f);
        *(__half2*)&sA[m][c4 * 4]     = __floats2half2_rn(v.x, v.y);
        *(__half2*)&sA[m][c4 * 4 + 2] = __floats2half2_rn(v.z, v.w);
    }
    // Stage W -> sB (fp32 -> fp16), row-major [k][n]
#pragma unroll
    for (int i = 0; i < 16; i++) {
        int idx = tid + i * 256;
        int k   = idx >> 5;
        int c4  = idx & 31;
        float4 v = *(const float4*)&W[(size_t)k * OUT_DIM + c4 * 4];
        *(__half2*)&sB[k][c4 * 4]     = __floats2half2_rn(v.x, v.y);
        *(__half2*)&sB[k][c4 * 4 + 2] = __floats2half2_rn(v.z, v.w);
    }
    __syncthreads();

    wmma::fragment<wmma::accumulator, 16, 16, 16, float> c[2][4];
#pragma unroll
    for (int i = 0; i < 2; i++)
#pragma unroll
        for (int j = 0; j < 4; j++)
            wmma::fill_fragment(c[i][j], 0.f);

#pragma unroll
    for (int k = 0; k < IN_DIM; k += 16) {
        wmma::fragment<wmma::matrix_a, 16, 16, 16, __half, wmma::row_major> a[2];
        wmma::fragment<wmma::matrix_b, 16, 16, 16, __half, wmma::row_major> b[4];
#pragma unroll
        for (int i = 0; i < 2; i++)
            wmma::load_matrix_sync(a[i], &sA[wm * 32 + i * 16][k], 136);
#pragma unroll
        for (int j = 0; j < 4; j++)
            wmma::load_matrix_sync(b[j], &sB[k][wn * 64 + j * 16], 136);
#pragma unroll
        for (int i = 0; i < 2; i++)
#pragma unroll
            for (int j = 0; j < 4; j++)
                wmma::mma_sync(c[i][j], a[i], b[j], c[i][j]);
    }

    // Epilogue: per-warp 16x16 float patch -> fp16 global
    const int r  = lane >> 1;           // 0..15
    const int c0 = (lane & 1) * 8;      // 0 or 8
#pragma unroll
    for (int i = 0; i < 2; i++) {
#pragma unroll
        for (int j = 0; j < 4; j++) {
            wmma::store_matrix_sync(&patch[warp][0][0], c[i][j], 16, wmma::mem_row_major);
            __syncwarp();
            float4 f0 = *(const float4*)&patch[warp][r][c0];
            float4 f1 = *(const float4*)&patch[warp][r][c0 + 4];
            __half2 h[4];
            h[0] = __floats2half2_rn(f0.x, f0.y);
            h[1] = __floats2half2_rn(f0.z, f0.w);
            h[2] = __floats2half2_rn(f1.x, f1.y);
            h[3] = __floats2half2_rn(f1.z, f1.w);
            int row = rowBase + wm * 32 + i * 16 + r;
            int col = wn * 64 + j * 16 + c0;
            if (row < N)
                *(uint4*)&H[(size_t)row * OUT_DIM + col] = *(uint4*)h;
            __syncwarp();
        }
    }
}

// ---------------------------------------------------------------------------
// CSR build
// ---------------------------------------------------------------------------
__global__ void __launch_bounds__(256)
zero_cnt_kernel(int N)
{
    int i = blockIdx.x * blockDim.x + threadIdx.x;
    if (i < N) g_cnt[i] = 0;
}

__global__ void __launch_bounds__(256)
hist_kernel(const int* __restrict__ dst, int E)
{
    int i = blockIdx.x * blockDim.x + threadIdx.x;
    int stride = gridDim.x * blockDim.x;
    for (; i < E; i += stride)
        atomicAdd(&g_cnt[dst[i]], 1);
}

__global__ void __launch_bounds__(SB)
blksum_kernel(int N)
{
    __shared__ int s[SB];
    int i = blockIdx.x * SB + threadIdx.x;
    s[threadIdx.x] = (i < N) ? g_cnt[i] : 0;
    __syncthreads();
#pragma unroll
    for (int d = SB / 2; d > 0; d >>= 1) {
        if (threadIdx.x < d) s[threadIdx.x] += s[threadIdx.x + d];
        __syncthreads();
    }
    if (threadIdx.x == 0) g_blk[blockIdx.x] = s[0];
}

__global__ void __launch_bounds__(MAX_BLKS)
blkscan_kernel(int nblk, int N, int E)
{
    __shared__ int s[MAX_BLKS];
    int t = threadIdx.x;
    int v = (t < nblk) ? g_blk[t] : 0;
    s[t] = v;
    __syncthreads();
#pragma unroll
    for (int d = 1; d < MAX_BLKS; d <<= 1) {
        int u = (t >= d) ? s[t - d] : 0;
        __syncthreads();
        s[t] += u;
        __syncthreads();
    }
    if (t < nblk) g_blkoff[t] = s[t] - v;
    if (t == 0) g_off[N] = E;
}

__global__ void __launch_bounds__(SB)
local_scan_kernel(int N)
{
    __shared__ int s[SB];
    int i = blockIdx.x * SB + threadIdx.x;
    int c = (i < N) ? g_cnt[i] : 0;
    s[threadIdx.x] = c;
    __syncthreads();
#pragma unroll
    for (int d = 1; d < SB; d <<= 1) {
        int u = (threadIdx.x >= d) ? s[threadIdx.x - d] : 0;
        __syncthreads();
        s[threadIdx.x] += u;
        __syncthreads();
    }
    if (i < N) {
        int off = g_blkoff[blockIdx.x] + s[threadIdx.x] - c;
        g_off[i] = off;
        g_cur[i] = off;
    }
}

__global__ void __launch_bounds__(256)
scatter_kernel(const int* __restrict__ src, const int* __restrict__ dst,
               const float* __restrict__ val, int E)
{
    int i = blockIdx.x * blockDim.x + threadIdx.x;
    int stride = gridDim.x * blockDim.x;
    for (; i < E; i += stride) {
        int d = dst[i];
        int pos = atomicAdd(&g_cur[d], 1);
        g_pairs[pos] = ((unsigned long long)__float_as_uint(val[i]) << 32)
                     | (unsigned int)src[i];
    }
}

// ---------------------------------------------------------------------------
// Aggregation: one warp per dst node, fp16 gather, 4-deep pipeline.
// ---------------------------------------------------------------------------
__global__ void __launch_bounds__(256)
agg_kernel(const __half* __restrict__ H, const float* __restrict__ bias,
           float* __restrict__ out, int N)
{
    const int lane = threadIdx.x & 31;
    const int w    = (blockIdx.x * blockDim.x + threadIdx.x) >> 5;
    if (w >= N) return;

    const int beg = g_off[w];
    const int end = g_off[w + 1];

    float4 acc0 = *(const float4*)&bias[lane * 4];
    float4 acc1 = make_float4(0.f, 0.f, 0.f, 0.f);

    int e = beg;
    unsigned long long p0 = 0, p1 = 0, p2 = 0, p3 = 0;
    if (e     < end) p0 = __ldg(&g_pairs[e]);
    if (e + 1 < end) p1 = __ldg(&g_pairs[e + 1]);
    if (e + 2 < end) p2 = __ldg(&g_pairs[e + 2]);
    if (e + 3 < end) p3 = __ldg(&g_pairs[e + 3]);

    while (e + 4 <= end) {
        const int   s0 = (int)(unsigned int)p0;
        const float v0 = __uint_as_float((unsigned int)(p0 >> 32));
        const int   s1 = (int)(unsigned int)p1;
        const float v1 = __uint_as_float((unsigned int)(p1 >> 32));
        const int   s2 = (int)(unsigned int)p2;
        const float v2 = __uint_as_float((unsigned int)(p2 >> 32));
        const int   s3 = (int)(unsigned int)p3;
        const float v3 = __uint_as_float((unsigned int)(p3 >> 32));

        const uint2 u0 = __ldg((const uint2*)(H + (size_t)s0 * OUT_DIM) + lane);
        const uint2 u1 = __ldg((const uint2*)(H + (size_t)s1 * OUT_DIM) + lane);
        const uint2 u2 = __ldg((const uint2*)(H + (size_t)s2 * OUT_DIM) + lane);
        const uint2 u3 = __ldg((const uint2*)(H + (size_t)s3 * OUT_DIM) + lane);

        p0 = (e + 4 < end) ? __ldg(&g_pairs[e + 4]) : 0ull;
        p1 = (e + 5 < end) ? __ldg(&g_pairs[e + 5]) : 0ull;
        p2 = (e + 6 < end) ? __ldg(&g_pairs[e + 6]) : 0ull;
        p3 = (e + 7 < end) ? __ldg(&g_pairs[e + 7]) : 0ull;

        float2 a0 = __half22float2(*(const __half2*)&u0.x);
        float2 b0 = __half22float2(*(const __half2*)&u0.y);
        float2 a1 = __half22float2(*(const __half2*)&u1.x);
        float2 b1 = __half22float2(*(const __half2*)&u1.y);
        float2 a2 = __half22float2(*(const __half2*)&u2.x);
        float2 b2 = __half22float2(*(const __half2*)&u2.y);
        float2 a3 = __half22float2(*(const __half2*)&u3.x);
        float2 b3 = __half22float2(*(const __half2*)&u3.y);

        acc0.x += v0 * a0.x; acc0.y += v0 * a0.y; acc0.z += v0 * b0.x; acc0.w += v0 * b0.y;
        acc1.x += v1 * a1.x; acc1.y += v1 * a1.y; acc1.z += v1 * b1.x; acc1.w += v1 * b1.y;
        acc0.x += v2 * a2.x; acc0.y += v2 * a2.y; acc0.z += v2 * b2.x; acc0.w += v2 * b2.y;
        acc1.x += v3 * a3.x; acc1.y += v3 * a3.y; acc1.z += v3 * b3.x; acc1.w += v3 * b3.y;
        e += 4;
    }
    // tail: p0..p2 hold pairs for remaining e..end-1 (at most 3)
    while (e < end) {
        const int   s0 = (int)(unsigned int)p0;
        const float v0 = __uint_as_float((unsigned int)(p0 >> 32));
        const uint2 u0 = __ldg((const uint2*)(H + (size_t)s0 * OUT_DIM) + lane);
        float2 a0 = __half22float2(*(const __half2*)&u0.x);
        float2 b0 = __half22float2(*(const __half2*)&u0.y);
        acc0.x += v0 * a0.x; acc0.y += v0 * a0.y;
        acc0.z += v0 * b0.x; acc0.w += v0 * b0.y;
        p0 = p1; p1 = p2;
        e++;
    }

    acc0.x += acc1.x; acc0.y += acc1.y; acc0.z += acc1.z; acc0.w += acc1.w;
    *(float4*)&out[(size_t)w * OUT_DIM + lane * 4] = acc0;
}

// ---------------------------------------------------------------------------
// Launch
// ---------------------------------------------------------------------------
extern "C" void kernel_launch(void* const* d_in, const int* in_sizes, int n_in,
                              void* d_out, int out_size)
{
    const float* features  = (const float*)d_in[0];
    const int*   edge_src  = (const int*)  d_in[1];
    const int*   edge_dst  = (const int*)  d_in[2];
    const float* edge_vals = (const float*)d_in[3];
    const float* weight    = (const float*)d_in[4];
    const float* bias      = (const float*)d_in[5];
    float*       out       = (float*)d_out;

    const int N = in_sizes[0] / IN_DIM;     // 100000
    const int E = in_sizes[1];              // 3200000

    __half* H;
    cudaGetSymbolAddress((void**)&H, g_H);

    // 1) H = X @ W  (tensor core, fp16 out)
    cudaFuncSetAttribute(gemm_kernel, cudaFuncAttributeMaxDynamicSharedMemorySize,
                         GEMM_SMEM);
    gemm_kernel<<<(N + 127) / 128, 256, GEMM_SMEM>>>(features, weight, H, N);

    // 2) CSR build
    int nblk = (N + SB - 1) / SB;           // 391
    zero_cnt_kernel<<<(N + 255) / 256, 256>>>(N);
    hist_kernel<<<1184, 256>>>(edge_dst, E);
    blksum_kernel<<<nblk, SB>>>(N);
    blkscan_kernel<<<1, MAX_BLKS>>>(nblk, N, E);
    local_scan_kernel<<<nblk, SB>>>(N);
    scatter_kernel<<<1184, 256>>>(edge_src, edge_dst, edge_vals, E);

    // 3) Aggregate: one warp per node (bias folded in)
    int agg_blocks = (N * 32 + 255) / 256;
    agg_kernel<<<agg_blocks, 256>>>(H, bias, out, N);
}

// round 6
// speedup vs baseline: 2.4646x; 1.0588x over previous
#include <cuda_runtime.h>
#include <cuda_fp16.h>
#include <cuda_bf16.h>
#include <mma.h>
#include <cstdint>

using namespace nvcuda;

// ---------------------------------------------------------------------------
// GCN layer: out = segment_sum((X @ W)[src] * val, dst) + bias
// N_NODES=100000, E=3200000, IN=OUT=128
// Tensor-core GEMM (fp16 in / fp32 accum / fp16 out) -> dst-CSR build ->
// fp16-gather aggregation: half-warp per edge (LDG.128), fp32 accum.
// ---------------------------------------------------------------------------

#define IN_DIM  128
#define OUT_DIM 128
#define MAX_NODES 100000
#define MAX_EDGES 3200000
#define SB 256
#define MAX_BLKS 512

// Scratch (device globals: allocation-free)
__device__ __half             g_H[(size_t)MAX_NODES * OUT_DIM];  // 25.6 MB fp16
__device__ int                g_cnt[MAX_NODES];
__device__ int                g_off[MAX_NODES + 1];
__device__ int                g_cur[MAX_NODES];
__device__ int                g_blk[MAX_BLKS];
__device__ int                g_blkoff[MAX_BLKS];
__device__ unsigned long long g_pairs[MAX_EDGES];                // (val<<32 | src)

// ---------------------------------------------------------------------------
// Kernel 1: H = X @ W  via wmma HMMA. Block = 128 rows, full K=128 in smem.
// ---------------------------------------------------------------------------
#define GEMM_SMEM (34816 + 34816 + 8192)

__global__ void __launch_bounds__(256, 2)
gemm_kernel(const float* __restrict__ X, const float* __restrict__ W,
            __half* __restrict__ H, int N)
{
    extern __shared__ char smem_raw[];
    __half (*sA)[136] = (__half(*)[136])(smem_raw);
    __half (*sB)[136] = (__half(*)[136])(smem_raw + 34816);
    float  (*patch)[16][16] = (float(*)[16][16])(smem_raw + 69632);

    const int tid  = threadIdx.x;
    const int lane = tid & 31;
    const int warp = tid >> 5;
    const int wm   = warp >> 1;
    const int wn   = warp & 1;
    const int rowBase = blockIdx.x * 128;

#pragma unroll
    for (int i = 0; i < 16; i++) {
        int idx = tid + i * 256;
        int m   = idx >> 5;
        int c4  = idx & 31;
        int row = rowBase + m;
        float4 v = (row < N) ? *(const float4*)&X[(size_t)row * IN_DIM + c4 * 4]
                             : make_float4(0.f, 0.f, 0.f, 0.f);
        *(__half2*)&sA[m][c4 * 4]     = __floats2half2_rn(v.x, v.y);
        *(__half2*)&sA[m][c4 * 4 + 2] = __floats2half2_rn(v.z, v.w);
    }
#pragma unroll
    for (int i = 0; i < 16; i++) {
        int idx = tid + i * 256;
        int k   = idx >> 5;
        int c4  = idx & 31;
        float4 v = *(const float4*)&W[(size_t)k * OUT_DIM + c4 * 4];
        *(__half2*)&sB[k][c4 * 4]     = __floats2half2_rn(v.x, v.y);
        *(__half2*)&sB[k][c4 * 4 + 2] = __floats2half2_rn(v.z, v.w);
    }
    __syncthreads();

    wmma::fragment<wmma::accumulator, 16, 16, 16, float> c[2][4];
#pragma unroll
    for (int i = 0; i < 2; i++)
#pragma unroll
        for (int j = 0; j < 4; j++)
            wmma::fill_fragment(c[i][j], 0.f);

#pragma unroll
    for (int k = 0; k < IN_DIM; k += 16) {
        wmma::fragment<wmma::matrix_a, 16, 16, 16, __half, wmma::row_major> a[2];
        wmma::fragment<wmma::matrix_b, 16, 16, 16, __half, wmma::row_major> b[4];
#pragma unroll
        for (int i = 0; i < 2; i++)
            wmma::load_matrix_sync(a[i], &sA[wm * 32 + i * 16][k], 136);
#pragma unroll
        for (int j = 0; j < 4; j++)
            wmma::load_matrix_sync(b[j], &sB[k][wn * 64 + j * 16], 136);
#pragma unroll
        for (int i = 0; i < 2; i++)
#pragma unroll
            for (int j = 0; j < 4; j++)
                wmma::mma_sync(c[i][j], a[i], b[j], c[i][j]);
    }

    const int r  = lane >> 1;
    const int c0 = (lane & 1) * 8;
#pragma unroll
    for (int i = 0; i < 2; i++) {
#pragma unroll
        for (int j = 0; j < 4; j++) {
            wmma::store_matrix_sync(&patch[warp][0][0], c[i][j], 16, wmma::mem_row_major);
            __syncwarp();
            float4 f0 = *(const float4*)&patch[warp][r][c0];
            float4 f1 = *(const float4*)&patch[warp][r][c0 + 4];
            __half2 h[4];
            h[0] = __floats2half2_rn(f0.x, f0.y);
            h[1] = __floats2half2_rn(f0.z, f0.w);
            h[2] = __floats2half2_rn(f1.x, f1.y);
            h[3] = __floats2half2_rn(f1.z, f1.w);
            int row = rowBase + wm * 32 + i * 16 + r;
            int col = wn * 64 + j * 16 + c0;
            if (row < N)
                *(uint4*)&H[(size_t)row * OUT_DIM + col] = *(uint4*)h;
            __syncwarp();
        }
    }
}

// ---------------------------------------------------------------------------
// CSR build
// ---------------------------------------------------------------------------
__global__ void __launch_bounds__(256)
zero_cnt_kernel(int N4)   // N4 = ceil(N/4)
{
    int i = blockIdx.x * blockDim.x + threadIdx.x;
    if (i < N4) ((int4*)g_cnt)[i] = make_int4(0, 0, 0, 0);
}

__global__ void __launch_bounds__(256)
hist_kernel(const int* __restrict__ dst, int E)
{
    int i = blockIdx.x * blockDim.x + threadIdx.x;
    int stride = gridDim.x * blockDim.x;
    int E4 = E >> 2;
    for (int b = i; b < E4; b += stride) {
        int4 d = __ldg((const int4*)dst + b);
        atomicAdd(&g_cnt[d.x], 1);
        atomicAdd(&g_cnt[d.y], 1);
        atomicAdd(&g_cnt[d.z], 1);
        atomicAdd(&g_cnt[d.w], 1);
    }
    // tail
    for (int e = (E4 << 2) + i; e < E; e += stride)
        atomicAdd(&g_cnt[dst[e]], 1);
}

__global__ void __launch_bounds__(SB)
blksum_kernel(int N)
{
    __shared__ int s[SB];
    int i = blockIdx.x * SB + threadIdx.x;
    s[threadIdx.x] = (i < N) ? g_cnt[i] : 0;
    __syncthreads();
#pragma unroll
    for (int d = SB / 2; d > 0; d >>= 1) {
        if (threadIdx.x < d) s[threadIdx.x] += s[threadIdx.x + d];
        __syncthreads();
    }
    if (threadIdx.x == 0) g_blk[blockIdx.x] = s[0];
}

__global__ void __launch_bounds__(MAX_BLKS)
blkscan_kernel(int nblk, int N, int E)
{
    __shared__ int s[MAX_BLKS];
    int t = threadIdx.x;
    int v = (t < nblk) ? g_blk[t] : 0;
    s[t] = v;
    __syncthreads();
#pragma unroll
    for (int d = 1; d < MAX_BLKS; d <<= 1) {
        int u = (t >= d) ? s[t - d] : 0;
        __syncthreads();
        s[t] += u;
        __syncthreads();
    }
    if (t < nblk) g_blkoff[t] = s[t] - v;
    if (t == 0) g_off[N] = E;
}

__global__ void __launch_bounds__(SB)
local_scan_kernel(int N)
{
    __shared__ int s[SB];
    int i = blockIdx.x * SB + threadIdx.x;
    int c = (i < N) ? g_cnt[i] : 0;
    s[threadIdx.x] = c;
    __syncthreads();
#pragma unroll
    for (int d = 1; d < SB; d <<= 1) {
        int u = (threadIdx.x >= d) ? s[threadIdx.x - d] : 0;
        __syncthreads();
        s[threadIdx.x] += u;
        __syncthreads();
    }
    if (i < N) {
        int off = g_blkoff[blockIdx.x] + s[threadIdx.x] - c;
        g_off[i] = off;
        g_cur[i] = off;
    }
}

__global__ void __launch_bounds__(256)
scatter_kernel(const int* __restrict__ src, const int* __restrict__ dst,
               const float* __restrict__ val, int E)
{
    int i = blockIdx.x * blockDim.x + threadIdx.x;
    int stride = gridDim.x * blockDim.x;
    int E4 = E >> 2;
    for (int b = i; b < E4; b += stride) {
        int4   s4 = __ldg((const int4*)src + b);
        int4   d4 = __ldg((const int4*)dst + b);
        float4 v4 = __ldg((const float4*)val + b);
        int p;
        p = atomicAdd(&g_cur[d4.x], 1);
        g_pairs[p] = ((unsigned long long)__float_as_uint(v4.x) << 32) | (unsigned int)s4.x;
        p = atomicAdd(&g_cur[d4.y], 1);
        g_pairs[p] = ((unsigned long long)__float_as_uint(v4.y) << 32) | (unsigned int)s4.y;
        p = atomicAdd(&g_cur[d4.z], 1);
        g_pairs[p] = ((unsigned long long)__float_as_uint(v4.z) << 32) | (unsigned int)s4.z;
        p = atomicAdd(&g_cur[d4.w], 1);
        g_pairs[p] = ((unsigned long long)__float_as_uint(v4.w) << 32) | (unsigned int)s4.w;
    }
    for (int e = (E4 << 2) + i; e < E; e += stride) {
        int pos = atomicAdd(&g_cur[dst[e]], 1);
        g_pairs[pos] = ((unsigned long long)__float_as_uint(val[e]) << 32)
                     | (unsigned int)src[e];
    }
}

// ---------------------------------------------------------------------------
// Aggregation: one warp per dst node; each HALF-WARP gathers one edge with
// LDG.128 (16 lanes x 16B = 256B row). Halves combine via shfl_xor(16).
// ---------------------------------------------------------------------------
__global__ void __launch_bounds__(256)
agg_kernel(const __half* __restrict__ H, const float* __restrict__ bias,
           float* __restrict__ out, int N)
{
    const int lane = threadIdx.x & 31;
    const int half = lane >> 4;          // which edge of the pair
    const int sub  = lane & 15;          // covers cols [sub*8, sub*8+8)
    const int w    = (blockIdx.x * blockDim.x + threadIdx.x) >> 5;
    if (w >= N) return;

    const int beg = g_off[w];
    const int end = g_off[w + 1];

    float acc[8];
    if (half == 0) {
        float4 b0 = *(const float4*)&bias[sub * 8];
        float4 b1 = *(const float4*)&bias[sub * 8 + 4];
        acc[0] = b0.x; acc[1] = b0.y; acc[2] = b0.z; acc[3] = b0.w;
        acc[4] = b1.x; acc[5] = b1.y; acc[6] = b1.z; acc[7] = b1.w;
    } else {
#pragma unroll
        for (int i = 0; i < 8; i++) acc[i] = 0.f;
    }

    int e = beg;
    unsigned long long p0 = 0, p1 = 0;   // p0 -> edge e+half, p1 -> edge e+2+half
    if (e + half     < end) p0 = __ldg(&g_pairs[e + half]);
    if (e + 2 + half < end) p1 = __ldg(&g_pairs[e + 2 + half]);

    while (e + 4 <= end) {
        const int   s0 = (int)(unsigned int)p0;
        const float v0 = __uint_as_float((unsigned int)(p0 >> 32));
        const int   s1 = (int)(unsigned int)p1;
        const float v1 = __uint_as_float((unsigned int)(p1 >> 32));

        const uint4 u0 = __ldg((const uint4*)(H + (size_t)s0 * OUT_DIM) + sub);
        const uint4 u1 = __ldg((const uint4*)(H + (size_t)s1 * OUT_DIM) + sub);

        p0 = (e + 4 + half < end) ? __ldg(&g_pairs[e + 4 + half]) : 0ull;
        p1 = (e + 6 + half < end) ? __ldg(&g_pairs[e + 6 + half]) : 0ull;

        float2 f;
        f = __half22float2(*(const __half2*)&u0.x); acc[0] += v0 * f.x; acc[1] += v0 * f.y;
        f = __half22float2(*(const __half2*)&u0.y); acc[2] += v0 * f.x; acc[3] += v0 * f.y;
        f = __half22float2(*(const __half2*)&u0.z); acc[4] += v0 * f.x; acc[5] += v0 * f.y;
        f = __half22float2(*(const __half2*)&u0.w); acc[6] += v0 * f.x; acc[7] += v0 * f.y;
        f = __half22float2(*(const __half2*)&u1.x); acc[0] += v1 * f.x; acc[1] += v1 * f.y;
        f = __half22float2(*(const __half2*)&u1.y); acc[2] += v1 * f.x; acc[3] += v1 * f.y;
        f = __half22float2(*(const __half2*)&u1.z); acc[4] += v1 * f.x; acc[5] += v1 * f.y;
        f = __half22float2(*(const __half2*)&u1.w); acc[6] += v1 * f.x; acc[7] += v1 * f.y;
        e += 4;
    }
    // tail: remaining end-e in {0,1,2,3}
    if (e + half < end) {
        const int   s0 = (int)(unsigned int)p0;
        const float v0 = __uint_as_float((unsigned int)(p0 >> 32));
        const uint4 u0 = __ldg((const uint4*)(H + (size_t)s0 * OUT_DIM) + sub);
        float2 f;
        f = __half22float2(*(const __half2*)&u0.x); acc[0] += v0 * f.x; acc[1] += v0 * f.y;
        f = __half22float2(*(const __half2*)&u0.y); acc[2] += v0 * f.x; acc[3] += v0 * f.y;
        f = __half22float2(*(const __half2*)&u0.z); acc[4] += v0 * f.x; acc[5] += v0 * f.y;
        f = __half22float2(*(const __half2*)&u0.w); acc[6] += v0 * f.x; acc[7] += v0 * f.y;
    }
    if (e + 2 + half < end) {
        const int   s1 = (int)(unsigned int)p1;
        const float v1 = __uint_as_float((unsigned int)(p1 >> 32));
        const uint4 u1 = __ldg((const uint4*)(H + (size_t)s1 * OUT_DIM) + sub);
        float2 f;
        f = __half22float2(*(const __half2*)&u1.x); acc[0] += v1 * f.x; acc[1] += v1 * f.y;
        f = __half22float2(*(const __half2*)&u1.y); acc[2] += v1 * f.x; acc[3] += v1 * f.y;
        f = __half22float2(*(const __half2*)&u1.z); acc[4] += v1 * f.x; acc[5] += v1 * f.y;
        f = __half22float2(*(const __half2*)&u1.w); acc[6] += v1 * f.x; acc[7] += v1 * f.y;
    }

    // combine halves (xor-16 butterfly: both halves end with full sums)
#pragma unroll
    for (int i = 0; i < 8; i++)
        acc[i] += __shfl_xor_sync(0xffffffff, acc[i], 16);

    // all 32 lanes store one float4: half 0 -> cols [sub*8, +4), half 1 -> [sub*8+4, +4)
    float4 o = (half == 0) ? make_float4(acc[0], acc[1], acc[2], acc[3])
                           : make_float4(acc[4], acc[5], acc[6], acc[7]);
    *(float4*)&out[(size_t)w * OUT_DIM + sub * 8 + half * 4] = o;
}

// ---------------------------------------------------------------------------
// Launch
// ---------------------------------------------------------------------------
extern "C" void kernel_launch(void* const* d_in, const int* in_sizes, int n_in,
                              void* d_out, int out_size)
{
    const float* features  = (const float*)d_in[0];
    const int*   edge_src  = (const int*)  d_in[1];
    const int*   edge_dst  = (const int*)  d_in[2];
    const float* edge_vals = (const float*)d_in[3];
    const float* weight    = (const float*)d_in[4];
    const float* bias      = (const float*)d_in[5];
    float*       out       = (float*)d_out;

    const int N = in_sizes[0] / IN_DIM;     // 100000
    const int E = in_sizes[1];              // 3200000

    __half* H;
    cudaGetSymbolAddress((void**)&H, g_H);

    // 1) H = X @ W  (tensor core, fp16 out)
    cudaFuncSetAttribute(gemm_kernel, cudaFuncAttributeMaxDynamicSharedMemorySize,
                         GEMM_SMEM);
    gemm_kernel<<<(N + 127) / 128, 256, GEMM_SMEM>>>(features, weight, H, N);

    // 2) CSR build
    int nblk = (N + SB - 1) / SB;           // 391
    int N4 = (N + 3) / 4;
    zero_cnt_kernel<<<(N4 + 255) / 256, 256>>>(N4);
    hist_kernel<<<592, 256>>>(edge_dst, E);
    blksum_kernel<<<nblk, SB>>>(N);
    blkscan_kernel<<<1, MAX_BLKS>>>(nblk, N, E);
    local_scan_kernel<<<nblk, SB>>>(N);
    scatter_kernel<<<592, 256>>>(edge_src, edge_dst, edge_vals, E);

    // 3) Aggregate: one warp per node (bias folded in)
    int agg_blocks = (N * 32 + 255) / 256;
    agg_kernel<<<agg_blocks, 256>>>(H, bias, out, N);
}